// round 1
// baseline (speedup 1.0000x reference)
#include <cuda_runtime.h>
#include <cstdint>

#define TILE 128
#define KT 16
#define MAXN 8192
#define MAXTILES (MAXN / TILE)

struct __align__(16) Top2 { float v1; int i1; float v2; int i2; };

// Scratch (no allocations allowed) — 16 MB partials + small decision arrays.
__device__ Top2 g_rowPart[MAXN * MAXTILES];
__device__ Top2 g_colPart[MAXN * MAXTILES];
__device__ int g_fwd_nn[MAXN];
__device__ int g_fwd_ok[MAXN];
__device__ int g_bck_nn[MAXN];
__device__ int g_bck_ok[MAXN];

// Stable top-2 insert: larger value wins; on exact tie, smaller index wins.
// Lexicographic rule makes the merge order-independent and matches
// jax.lax.top_k's stable tie-breaking.
__device__ __forceinline__ void t2_ins(float& v1, int& i1, float& v2, int& i2,
                                       float v, int i) {
    if (v > v1 || (v == v1 && i < i1)) { v2 = v1; i2 = i1; v1 = v; i1 = i; }
    else if (v > v2 || (v == v2 && i < i2)) { v2 = v; i2 = i; }
}

// Duplicate one f32 into both lanes of an f32x2 register pair.
__device__ __forceinline__ unsigned long long dup2(float a) {
    unsigned long long r;
    unsigned ai = __float_as_uint(a);
    asm("mov.b64 %0, {%1, %1};" : "=l"(r) : "r"(ai));
    return r;
}

// Packed fp32 FMA (Blackwell FFMA2) — 2 FMAs per instruction.
__device__ __forceinline__ void fma2(unsigned long long& acc,
                                     unsigned long long a, unsigned long long b) {
    asm("fma.rn.f32x2 %0, %1, %2, %0;" : "+l"(acc) : "l"(a), "l"(b));
}

__device__ __forceinline__ void cp16(float* s, const float* g) {
    unsigned ss = (unsigned)__cvta_generic_to_shared(s);
    asm volatile("cp.async.cg.shared.global [%0], [%1], 16;" :: "r"(ss), "l"(g));
}

// dot[n, m] = sum_f A[f, n] * B[f, m]   (A: [K, N] row-major, B: [K, M] row-major)
// One CTA: 128x128 output tile, 256 threads, 8x8 micro-tile per thread.
// Epilogue: per-tile row top-2 and col top-2 partials written to scratch.
extern __shared__ float pool[];   // 16384 floats = 64 KB (pipeline + C tile, reused)

__global__ void __launch_bounds__(256, 2)
gemm_top2(const float* __restrict__ A, const float* __restrict__ B,
          int N, int M, int K)
{
    const int tid = threadIdx.x;
    const int tx = tid & 15, ty = tid >> 4;
    const int mBase = blockIdx.x * TILE;
    const int nBase = blockIdx.y * TILE;
    const int mTiles = M / TILE, nTiles = N / TILE;

    float* sA = pool;                   // [2][KT][TILE]
    float* sB = pool + 2 * KT * TILE;   // [2][KT][TILE]

    unsigned long long acc[8][4];
#pragma unroll
    for (int r = 0; r < 8; r++)
#pragma unroll
        for (int c = 0; c < 4; c++) acc[r][c] = 0ull;

    const float* Ag = A + nBase;
    const float* Bg = B + mBase;
    const int nkt = K / KT;

    // Prefetch stage 0 into buffer 0
#pragma unroll
    for (int r = 0; r < 2; r++) {
        int q = tid + r * 256;
        int kk = q >> 5, c4 = (q & 31) << 2;
        cp16(&sA[kk * TILE + c4], Ag + (size_t)kk * N + c4);
        cp16(&sB[kk * TILE + c4], Bg + (size_t)kk * M + c4);
    }
    asm volatile("cp.async.commit_group;");

    for (int kt = 0; kt < nkt; kt++) {
        const int buf = kt & 1;
        __syncthreads();   // everyone done reading buf^1 before we overwrite it
        if (kt + 1 < nkt) {
            int k0 = (kt + 1) * KT;
            float* dA = sA + (buf ^ 1) * KT * TILE;
            float* dB = sB + (buf ^ 1) * KT * TILE;
#pragma unroll
            for (int r = 0; r < 2; r++) {
                int q = tid + r * 256;
                int kk = q >> 5, c4 = (q & 31) << 2;
                cp16(&dA[kk * TILE + c4], Ag + (size_t)(k0 + kk) * N + c4);
                cp16(&dB[kk * TILE + c4], Bg + (size_t)(k0 + kk) * M + c4);
            }
            asm volatile("cp.async.commit_group;");
            asm volatile("cp.async.wait_group 1;");
        } else {
            asm volatile("cp.async.wait_group 0;");
        }
        __syncthreads();

        const float* bA = sA + buf * KT * TILE + ty * 8;
        const float* bB = sB + buf * KT * TILE + tx * 8;
#pragma unroll
        for (int kk = 0; kk < KT; kk++) {
            float4 a0 = *(const float4*)(bA + kk * TILE);
            float4 a1 = *(const float4*)(bA + kk * TILE + 4);
            ulonglong2 b0 = *(const ulonglong2*)(bB + kk * TILE);
            ulonglong2 b1 = *(const ulonglong2*)(bB + kk * TILE + 4);
            unsigned long long ad[8];
            ad[0] = dup2(a0.x); ad[1] = dup2(a0.y); ad[2] = dup2(a0.z); ad[3] = dup2(a0.w);
            ad[4] = dup2(a1.x); ad[5] = dup2(a1.y); ad[6] = dup2(a1.z); ad[7] = dup2(a1.w);
            unsigned long long bp[4] = { b0.x, b0.y, b1.x, b1.y };
#pragma unroll
            for (int r = 0; r < 8; r++)
#pragma unroll
                for (int c = 0; c < 4; c++)
                    fma2(acc[r][c], ad[r], bp[c]);
        }
    }

    // ---- Epilogue: dump C tile to smem (pipeline buffers dead now) ----
    __syncthreads();
    unsigned long long* poolU = (unsigned long long*)pool;
#pragma unroll
    for (int r = 0; r < 8; r++) {
        int row = ty * 8 + r;
#pragma unroll
        for (int c = 0; c < 4; c++)
            poolU[(row * TILE + tx * 8) / 2 + c] = acc[r][c];
    }
    __syncthreads();

    // Row top-2 over this tile: 2 threads per row, merge via shfl.
    {
        int row = tid >> 1, half = tid & 1;
        float v1 = -1e30f, v2 = -1e30f; int i1 = 0x7fffffff, i2 = 0x7fffffff;
        const float* rp = pool + row * TILE + half * 64;
        int ibase = mBase + half * 64;
#pragma unroll 8
        for (int c = 0; c < 64; c++) t2_ins(v1, i1, v2, i2, rp[c], ibase + c);
        float pv1 = __shfl_xor_sync(0xffffffffu, v1, 1);
        int   pi1 = __shfl_xor_sync(0xffffffffu, i1, 1);
        float pv2 = __shfl_xor_sync(0xffffffffu, v2, 1);
        int   pi2 = __shfl_xor_sync(0xffffffffu, i2, 1);
        t2_ins(v1, i1, v2, i2, pv1, pi1);
        t2_ins(v1, i1, v2, i2, pv2, pi2);
        if (half == 0) {
            Top2 o; o.v1 = v1; o.i1 = i1; o.v2 = v2; o.i2 = i2;
            g_rowPart[(size_t)(nBase + row) * mTiles + blockIdx.x] = o;
        }
    }
    // Col top-2 over this tile.
    {
        int col = tid >> 1, half = tid & 1;
        float v1 = -1e30f, v2 = -1e30f; int i1 = 0x7fffffff, i2 = 0x7fffffff;
        const float* cp = pool + (half * 64) * TILE + col;
        int ibase = nBase + half * 64;
#pragma unroll 8
        for (int r = 0; r < 64; r++) t2_ins(v1, i1, v2, i2, cp[r * TILE], ibase + r);
        float pv1 = __shfl_xor_sync(0xffffffffu, v1, 1);
        int   pi1 = __shfl_xor_sync(0xffffffffu, i1, 1);
        float pv2 = __shfl_xor_sync(0xffffffffu, v2, 1);
        int   pi2 = __shfl_xor_sync(0xffffffffu, i2, 1);
        t2_ins(v1, i1, v2, i2, pv1, pi1);
        t2_ins(v1, i1, v2, i2, pv2, pi2);
        if (half == 0) {
            Top2 o; o.v1 = v1; o.i1 = i1; o.v2 = v2; o.i2 = i2;
            g_colPart[(size_t)(mBase + col) * nTiles + blockIdx.y] = o;
        }
    }
}

// Reduce the per-tile partials to global top-2 per row/col and apply the
// ratio test on the clamped distance: pass iff max(1-v1,1e-6) < max(1-v2,1e-6).
__global__ void reduce_top2(int which, int tiles, int n)
{
    const Top2* part = which ? g_colPart : g_rowPart;
    int* nn = which ? g_bck_nn : g_fwd_nn;
    int* ok = which ? g_bck_ok : g_fwd_ok;

    int warp = (blockIdx.x * blockDim.x + threadIdx.x) >> 5;
    int lane = threadIdx.x & 31;
    if (warp >= n) return;

    float v1 = -1e30f, v2 = -1e30f; int i1 = 0x7fffffff, i2 = 0x7fffffff;
    for (int p = lane; p < tiles; p += 32) {
        Top2 q = part[(size_t)warp * tiles + p];
        t2_ins(v1, i1, v2, i2, q.v1, q.i1);
        t2_ins(v1, i1, v2, i2, q.v2, q.i2);
    }
    for (int off = 16; off > 0; off >>= 1) {
        float qv1 = __shfl_xor_sync(0xffffffffu, v1, off);
        int   qi1 = __shfl_xor_sync(0xffffffffu, i1, off);
        float qv2 = __shfl_xor_sync(0xffffffffu, v2, off);
        int   qi2 = __shfl_xor_sync(0xffffffffu, i2, off);
        t2_ins(v1, i1, v2, i2, qv1, qi1);
        t2_ins(v1, i1, v2, i2, qv2, qi2);
    }
    if (lane == 0) {
        float c1 = fmaxf(1.0f - v1, 1e-6f);
        float c2 = fmaxf(1.0f - v2, 1e-6f);
        nn[warp] = i1;
        ok[warp] = (c1 < c2) ? 1 : 0;
    }
}

// Outputs concatenated as float32:
//   [0, n):   indices0 (mutual ? fwd_nn : -1)
//   [n, 2n):  matches1 = -1
//   [2n, 3n): mscores0 = (indices0 > 0) ? 1 : 0     (strict >, per reference)
//   [3n, 4n): mscores1 = 0
__global__ void finalize(float* __restrict__ out, int n, int out_size)
{
    int e = blockIdx.x * blockDim.x + threadIdx.x;
    if (e >= out_size) return;
    int seg = e / n, i = e - seg * n;
    float val = 0.0f;
    if (seg == 0 || seg == 2) {
        int j = g_fwd_nn[i];
        bool mutual = g_fwd_ok[i] && g_bck_ok[j] && (g_bck_nn[j] == i);
        int idx = mutual ? j : -1;
        val = (seg == 0) ? (float)idx : ((idx > 0) ? 1.0f : 0.0f);
    } else if (seg == 1) {
        val = -1.0f;
    }
    out[e] = val;
}

extern "C" void kernel_launch(void* const* d_in, const int* in_sizes, int n_in,
                              void* d_out, int out_size)
{
    const float* d0 = (const float*)d_in[0];   // [K, N] fp32
    const float* d1 = (const float*)d_in[1];   // [K, M] fp32
    int N = in_sizes[2] / 2;                   // keypoints0: [N, 2]
    int M = in_sizes[3] / 2;                   // keypoints1: [M, 2]
    int K = in_sizes[0] / N;                   // 256

    cudaFuncSetAttribute(gemm_top2, cudaFuncAttributeMaxDynamicSharedMemorySize, 65536);

    dim3 grid(M / TILE, N / TILE);
    gemm_top2<<<grid, 256, 65536>>>(d0, d1, N, M, K);

    reduce_top2<<<(N * 32 + 255) / 256, 256>>>(0, M / TILE, N);
    reduce_top2<<<(M * 32 + 255) / 256, 256>>>(1, N / TILE, M);

    finalize<<<(out_size + 255) / 256, 256>>>((float*)d_out, N, out_size);
}